// round 4
// baseline (speedup 1.0000x reference)
#include <cuda_runtime.h>
#include <math.h>

// Problem dims (fixed by the reference)
#define BB  8
#define HH  384
#define WW  768
#define HW_ (HH * WW)        // 294912
#define BHW (BB * HW_)       // 2359296

// ---------------------------------------------------------------------------
// Scratch (static __device__ arrays: no runtime allocation)
// ---------------------------------------------------------------------------
__device__ double g_acc[6];
// 0: photo_fw_sum, 1: photo_bw_sum, 2: mask_fw_sum, 3: mask_bw_sum,
// 4: census_fw_sum, 5: census_bw_sum

__device__ float g_inten1 [BHW];  // gray(img1)*255
__device__ float g_inten2w[BHW];  // gray(warp(img2, flow_fw))*255
__device__ float g_inten2 [BHW];  // gray(img2)*255
__device__ float g_inten1w[BHW];  // gray(warp(img1, flow_bw))*255
__device__ float g_mask_fw[BHW];
__device__ float g_mask_bw[BHW];

// ---------------------------------------------------------------------------
// Helpers
// ---------------------------------------------------------------------------
__device__ __forceinline__ float warp_red(float v) {
#pragma unroll
    for (int o = 16; o > 0; o >>= 1) v += __shfl_down_sync(0xFFFFFFFFu, v, o);
    return v;
}

// bilinear coords (align_corners=True, border padding == clamp)
__device__ __forceinline__ void bilin(float gx, float gy,
                                      int& i00, int& i01, int& i10, int& i11,
                                      float& w00, float& w01, float& w10, float& w11) {
    gx = fminf(fmaxf(gx, 0.0f), (float)(WW - 1));
    gy = fminf(fmaxf(gy, 0.0f), (float)(HH - 1));
    float x0 = floorf(gx);
    float y0 = floorf(gy);
    float wx = gx - x0;
    float wy = gy - y0;
    int x0i = (int)x0;
    int y0i = (int)y0;
    int x1i = min(x0i + 1, WW - 1);
    int y1i = min(y0i + 1, HH - 1);
    i00 = y0i * WW + x0i;
    i01 = y0i * WW + x1i;
    i10 = y1i * WW + x0i;
    i11 = y1i * WW + x1i;
    w00 = (1.0f - wx) * (1.0f - wy);
    w01 = wx * (1.0f - wy);
    w10 = (1.0f - wx) * wy;
    w11 = wx * wy;
}

__device__ __forceinline__ float gather4(const float* __restrict__ p,
                                         int i00, int i01, int i10, int i11,
                                         float w00, float w01, float w10, float w11) {
    return __ldg(p + i00) * w00 + __ldg(p + i01) * w01 +
           __ldg(p + i10) * w10 + __ldg(p + i11) * w11;
}

// ---------------------------------------------------------------------------
// K0: zero accumulators
// ---------------------------------------------------------------------------
__global__ void k_zero() {
    if (threadIdx.x < 6) g_acc[threadIdx.x] = 0.0;
}

// ---------------------------------------------------------------------------
// K1: warps, occlusion masks, photometric loss terms, intensity planes
// grid = BHW/256, block = 256 (exact division)
// ---------------------------------------------------------------------------
__global__ __launch_bounds__(256) void k_warp(
    const float* __restrict__ img1, const float* __restrict__ img2,
    const float* __restrict__ ffw,  const float* __restrict__ fbw,
    float* __restrict__ occ_out) {

    const int idx = blockIdx.x * blockDim.x + threadIdx.x;  // < BHW exactly
    const int b = idx / HW_;
    const int r = idx - b * HW_;
    const int y = r / WW;
    const int x = r - y * WW;

    const float* ffb = ffw + b * 2 * HW_;
    const float* fbb = fbw + b * 2 * HW_;
    const float ffx = __ldg(ffb + r);
    const float ffy = __ldg(ffb + HW_ + r);
    const float fbx = __ldg(fbb + r);
    const float fby = __ldg(fbb + HW_ + r);

    // ---- forward-flow coordinates: warp img2 and flow_bw ----
    int a00, a01, a10, a11; float u00, u01, u10, u11;
    bilin(ffx + (float)x, ffy + (float)y, a00, a01, a10, a11, u00, u01, u10, u11);
    const float* i2b = img2 + b * 3 * HW_;
    float i2w0 = gather4(i2b,            a00, a01, a10, a11, u00, u01, u10, u11);
    float i2w1 = gather4(i2b + HW_,      a00, a01, a10, a11, u00, u01, u10, u11);
    float i2w2 = gather4(i2b + 2 * HW_,  a00, a01, a10, a11, u00, u01, u10, u11);
    float fbw_wx = gather4(fbb,          a00, a01, a10, a11, u00, u01, u10, u11);
    float fbw_wy = gather4(fbb + HW_,    a00, a01, a10, a11, u00, u01, u10, u11);

    // ---- backward-flow coordinates: warp img1 and flow_fw ----
    int c00, c01, c10, c11; float v00, v01, v10, v11;
    bilin(fbx + (float)x, fby + (float)y, c00, c01, c10, c11, v00, v01, v10, v11);
    const float* i1b = img1 + b * 3 * HW_;
    float i1w0 = gather4(i1b,            c00, c01, c10, c11, v00, v01, v10, v11);
    float i1w1 = gather4(i1b + HW_,      c00, c01, c10, c11, v00, v01, v10, v11);
    float i1w2 = gather4(i1b + 2 * HW_,  c00, c01, c10, c11, v00, v01, v10, v11);
    float ffw_wx = gather4(ffb,          c00, c01, c10, c11, v00, v01, v10, v11);
    float ffw_wy = gather4(ffb + HW_,    c00, c01, c10, c11, v00, v01, v10, v11);

    // ---- occlusion masks ----
    float d0 = ffx + fbw_wx, d1 = ffy + fbw_wy;
    float mag_f = d0 * d0 + d1 * d1;
    float fm_f = (ffx * ffx + ffy * ffy) + (fbw_wx * fbw_wx + fbw_wy * fbw_wy);
    float occ_f = (mag_f > 0.01f * fm_f + 0.5f) ? 1.0f : 0.0f;
    float mfw = 1.0f - occ_f;

    float e0 = fbx + ffw_wx, e1 = fby + ffw_wy;
    float mag_b = e0 * e0 + e1 * e1;
    float fm_b = (fbx * fbx + fby * fby) + (ffw_wx * ffw_wx + ffw_wy * ffw_wy);
    float occ_b = (mag_b > 0.01f * fm_b + 0.5f) ? 1.0f : 0.0f;
    float mbw = 1.0f - occ_b;

    // ---- photometric terms ----
    float i1c0 = __ldg(i1b + r);
    float i1c1 = __ldg(i1b + HW_ + r);
    float i1c2 = __ldg(i1b + 2 * HW_ + r);
    float i2c0 = __ldg(i2b + r);
    float i2c1 = __ldg(i2b + HW_ + r);
    float i2c2 = __ldg(i2b + 2 * HW_ + r);

    float pfw = (__powf(fabsf(i1c0 - i2w0) + 0.01f, 0.4f) +
                 __powf(fabsf(i1c1 - i2w1) + 0.01f, 0.4f) +
                 __powf(fabsf(i1c2 - i2w2) + 0.01f, 0.4f)) * mfw;
    float pbw = (__powf(fabsf(i2c0 - i1w0) + 0.01f, 0.4f) +
                 __powf(fabsf(i2c1 - i1w1) + 0.01f, 0.4f) +
                 __powf(fabsf(i2c2 - i1w2) + 0.01f, 0.4f)) * mbw;

    // ---- intensity planes (gray*255) ----
    g_inten1 [idx] = (0.2989f * i1c0 + 0.587f * i1c1 + 0.114f * i1c2) * 255.0f;
    g_inten2 [idx] = (0.2989f * i2c0 + 0.587f * i2c1 + 0.114f * i2c2) * 255.0f;
    g_inten2w[idx] = (0.2989f * i2w0 + 0.587f * i2w1 + 0.114f * i2w2) * 255.0f;
    g_inten1w[idx] = (0.2989f * i1w0 + 0.587f * i1w1 + 0.114f * i1w2) * 255.0f;
    g_mask_fw[idx] = mfw;
    g_mask_bw[idx] = mbw;
    occ_out[idx] = occ_f;

    // ---- block reduce 4 scalars, one double atomic each per block ----
    __shared__ float red[4][8];
    const int wid = threadIdx.x >> 5;
    const int lane = threadIdx.x & 31;
    float vals[4] = {pfw, pbw, mfw, mbw};
#pragma unroll
    for (int i = 0; i < 4; i++) {
        float v = warp_red(vals[i]);
        if (lane == 0) red[i][wid] = v;
    }
    __syncthreads();
    if (wid == 0) {
#pragma unroll
        for (int i = 0; i < 4; i++) {
            float v = (lane < 8) ? red[i][lane] : 0.0f;
            v = warp_red(v);
            if (lane == 0) atomicAdd(&g_acc[i], (double)v);
        }
    }
}

// ---------------------------------------------------------------------------
// K2: census loss. grid = (W/32, H/8, 2*B), block = (32, 8)
// z: b = z&7, pair = z>>3 (0: fw (inten1 vs inten2w), 1: bw (inten2 vs inten1w))
// ---------------------------------------------------------------------------
__global__ __launch_bounds__(256) void k_census() {
    const int z = blockIdx.z;
    const int b = z & 7;
    const int pair = z >> 3;

    const float* __restrict__ A = (pair ? g_inten2  : g_inten1 ) + b * HW_;
    const float* __restrict__ Bp = (pair ? g_inten1w : g_inten2w) + b * HW_;
    const float* __restrict__ M = (pair ? g_mask_bw : g_mask_fw) + b * HW_;

    __shared__ float sA[14][38];
    __shared__ float sB[14][38];

    const int gx0 = blockIdx.x * 32 - 3;
    const int gy0 = blockIdx.y * 8 - 3;
    const int tid = threadIdx.y * 32 + threadIdx.x;

    for (int i = tid; i < 14 * 38; i += 256) {
        int ly = i / 38;
        int lx = i - ly * 38;
        int gy = gy0 + ly;
        int gx = gx0 + lx;
        bool in = (gx >= 0) & (gx < WW) & (gy >= 0) & (gy < HH);
        int g = gy * WW + gx;
        sA[ly][lx] = in ? __ldg(A + g) : 0.0f;
        sB[ly][lx] = in ? __ldg(Bp + g) : 0.0f;
    }
    __syncthreads();

    const int tx = threadIdx.x, ty = threadIdx.y;
    const float cA = sA[ty + 3][tx + 3];
    const float cB = sB[ty + 3][tx + 3];

    float acc = 0.0f;
#pragma unroll
    for (int dy = 0; dy < 7; dy++) {
#pragma unroll
        for (int dx = 0; dx < 7; dx++) {
            if (dy == 3 && dx == 3) continue;  // center term is exactly 0
            float dA = sA[ty + dy][tx + dx] - cA;
            float dB = sB[ty + dy][tx + dx] - cB;
            float tA = dA * rsqrtf(fmaf(dA, dA, 0.81f));
            float tB = dB * rsqrtf(fmaf(dB, dB, 0.81f));
            float dt = tA - tB;
            float q = dt * dt;
            acc += __fdividef(q, 0.1f + q);
        }
    }

    const int px = blockIdx.x * 32 + tx;
    const int py = blockIdx.y * 8 + ty;
    float m = __ldg(M + py * WW + px);
    float val = __powf(acc + 0.01f, 0.4f) * m;

    // block reduce -> one double atomic
    __shared__ float red[8];
    const int wid = tid >> 5;
    const int lane = tid & 31;
    float v = warp_red(val);
    if (lane == 0) red[wid] = v;
    __syncthreads();
    if (wid == 0) {
        float w = (lane < 8) ? red[lane] : 0.0f;
        w = warp_red(w);
        if (lane == 0) atomicAdd(&g_acc[4 + pair], (double)w);
    }
}

// ---------------------------------------------------------------------------
// K3: finalize scalars
// ---------------------------------------------------------------------------
__global__ void k_final(float* __restrict__ out) {
    double den_fw = 2.0 * g_acc[2] + 1e-6;
    double den_bw = 2.0 * g_acc[3] + 1e-6;
    double photo  = g_acc[0] / den_fw + g_acc[1] / den_bw;
    double census = g_acc[4] / den_fw + g_acc[5] / den_bw;
    out[0] = (float)(photo + census);
    out[1] = (float)photo;
    out[2] = (float)census;
}

// ---------------------------------------------------------------------------
// Launch
// ---------------------------------------------------------------------------
extern "C" void kernel_launch(void* const* d_in, const int* in_sizes, int n_in,
                              void* d_out, int out_size) {
    const float* img1 = (const float*)d_in[0];
    const float* img2 = (const float*)d_in[1];
    const float* ffw  = (const float*)d_in[2];
    const float* fbw  = (const float*)d_in[3];
    float* out = (float*)d_out;

    (void)in_sizes; (void)n_in; (void)out_size;

    k_zero<<<1, 32>>>();
    k_warp<<<BHW / 256, 256>>>(img1, img2, ffw, fbw, out + 3);
    dim3 g2(WW / 32, HH / 8, 2 * BB);
    dim3 b2(32, 8, 1);
    k_census<<<g2, b2>>>();
    k_final<<<1, 1>>>(out);
}